// round 4
// baseline (speedup 1.0000x reference)
#include <cuda_runtime.h>
#include <math.h>

// ---------------------------------------------------------------------------
// KANConvNet round 3: 9-row packed weights + clamped sparse window,
// single-pass OT=16 tiles, padded SMEM row stride (bank-conflict-free),
// merged pack kernel, unrolled classifier.
//
// Packed weights [i][9][OUT]: row 0 = base_w (coef silu(x)),
// row 1+j = sw[o][i][j]*sc[o][i] (j=0..7). For knot cell m=floor((x+2.2)/0.4),
// nonzero spline rows are 1+clamp(m-3+t,0,7), t=0..3, coef w_t masked by
// window validity.
// ---------------------------------------------------------------------------

__device__ float g_wp0[147 * 9 * 16];
__device__ float g_wp1[144 * 9 * 32];
__device__ float g_wp2[288 * 9 * 64];
__device__ float g_wpc[64  * 9 * 200];

__device__ float g_a0[8 * 16 * 112 * 112];
__device__ float g_p0[8 * 16 * 56 * 56];
__device__ float g_a1[8 * 32 * 28 * 28];
__device__ float g_p1[8 * 32 * 14 * 14];
__device__ float g_a2[8 * 64 * 7 * 7];

#define N0P (147 * 9 * 16)
#define N1P (144 * 9 * 32)
#define N2P (288 * 9 * 64)
#define NCP (64  * 9 * 200)

// ---------------- packed f32x2 helpers ----------------
__device__ __forceinline__ long long pk2(float a) {
    long long r;
    asm("mov.b64 %0, {%1, %1};" : "=l"(r) : "f"(a));
    return r;
}
__device__ __forceinline__ long long ffma2(long long a, long long b, long long c) {
    long long d;
    asm("fma.rn.f32x2 %0, %1, %2, %3;" : "=l"(d) : "l"(a), "l"(b), "l"(c));
    return d;
}
__device__ __forceinline__ float2 upk2(long long a) {
    float x, y;
    asm("mov.b64 {%0, %1}, %2;" : "=f"(x), "=f"(y) : "l"(a));
    return make_float2(x, y);
}

// ---------------- coefficient evaluation ----------------
// c0 = silu(x); w[t] = masked cardinal cubic weight; r[t] = row index (1..8).
__device__ __forceinline__ void eval5(float x, float& c0, float* w, int* r) {
    float sig = 1.0f / (1.0f + __expf(-x));
    c0 = x * sig;
    float t  = fmaf(x, 2.5f, 5.5f);         // (x + 2.2) / 0.4
    float mf = floorf(t);
    bool inr = (mf >= 0.0f) && (mf <= 10.0f);
    mf = fminf(fmaxf(mf, 0.0f), 10.0f);
    float u  = t - mf;
    float u2 = u * u;
    float u3 = u2 * u;
    float om = 1.0f - u;
    const float s6 = 1.0f / 6.0f;
    float a0 = s6 * om * om * om;
    float a1 = s6 * fmaf(3.0f, u3, fmaf(-6.0f, u2, 4.0f));
    float a2 = s6 * fmaf(-3.0f, u3, fmaf(3.0f, u2, fmaf(3.0f, u, 1.0f)));
    float a3 = s6 * u3;
    int m = (int)mf;
    w[0] = (inr && m >= 3)            ? a0 : 0.0f;
    w[1] = (inr && m >= 2 && m <= 9)  ? a1 : 0.0f;
    w[2] = (inr && m >= 1 && m <= 8)  ? a2 : 0.0f;
    w[3] = (inr && m <= 7)            ? a3 : 0.0f;
#pragma unroll
    for (int t4 = 0; t4 < 4; t4++) {
        int j = m - 3 + t4;
        j = j < 0 ? 0 : (j > 7 ? 7 : j);
        r[t4] = 1 + j;
    }
}

// ---------------- merged weight packing ----------------
__device__ __forceinline__ void pack_one(int idx,
                                         const float* __restrict__ bw,
                                         const float* __restrict__ sw,
                                         const float* __restrict__ sc,
                                         float* __restrict__ wp,
                                         int OUT, int IN) {
    int i   = idx / (9 * OUT);
    int rem = idx - i * 9 * OUT;
    int r   = rem / OUT;
    int o   = rem - r * OUT;
    int oi  = o * IN + i;
    float v = (r == 0) ? bw[oi] : sw[oi * 8 + (r - 1)] * sc[oi];
    wp[idx] = v;
}

__global__ void pack_all(const float* bw0, const float* sw0, const float* sc0,
                         const float* bw1, const float* sw1, const float* sc1,
                         const float* bw2, const float* sw2, const float* sc2,
                         const float* bwc, const float* swc, const float* scc,
                         float* wp0, float* wp1, float* wp2, float* wpc) {
    int idx = blockIdx.x * blockDim.x + threadIdx.x;
    if (idx < N0P) { pack_one(idx, bw0, sw0, sc0, wp0, 16, 147); return; }
    idx -= N0P;
    if (idx < N1P) { pack_one(idx, bw1, sw1, sc1, wp1, 32, 144); return; }
    idx -= N1P;
    if (idx < N2P) { pack_one(idx, bw2, sw2, sc2, wp2, 64, 288); return; }
    idx -= N2P;
    if (idx < NCP) { pack_one(idx, bwc, swc, scc, wpc, 200, 64); }
}

// ---------------------------------------------------------------------------
// Fused KAN conv layer. Thread = one position, OT outputs in registers.
// SMEM weight tile [INF][9][RSTR] with RSTR padded for conflict-free windows.
// ---------------------------------------------------------------------------
template <int CIN, int K, int S, int P, int OUT, int OT, int T, int RSTR>
__global__ void __launch_bounds__(T)
kan_conv(const float* __restrict__ in,
         const float* __restrict__ wp,
         float* __restrict__ out,
         int B, int H, int W, int Ho, int Wo) {
    extern __shared__ float swm[];   // [INF][9][RSTR]
    const int INF = CIN * K * K;
    const int ot  = blockIdx.y;

    for (int idx = threadIdx.x; idx < INF * 9 * OT; idx += T) {
        int i   = idx / (9 * OT);
        int rem = idx - i * 9 * OT;
        int r   = rem / OT;
        int o   = rem - r * OT;
        swm[(i * 9 + r) * RSTR + o] = wp[(i * 9 + r) * OUT + ot * OT + o];
    }
    __syncthreads();

    const int N = B * Ho * Wo;
    int gp      = blockIdx.x * T + threadIdx.x;
    bool valid  = gp < N;
    int gpc     = valid ? gp : 0;
    int b  = gpc / (Ho * Wo);
    int rr = gpc - b * Ho * Wo;
    int ho = rr / Wo;
    int wo = rr - ho * Wo;
    int hb = ho * S - P;
    int wb = wo * S - P;
    const float* inb = in + (long long)b * CIN * H * W;

    long long acc[OT / 2];
#pragma unroll
    for (int k = 0; k < OT / 2; k++) acc[k] = 0LL;

    const float* swr = swm;
#pragma unroll 1
    for (int c = 0; c < CIN; c++) {
#pragma unroll 1
        for (int kh = 0; kh < K; kh++) {
            int hin = hb + kh;
            const float* row = inb + ((long long)c * H + hin) * W;
            bool hok = valid && (hin >= 0) && (hin < H);
#pragma unroll
            for (int kw = 0; kw < K; kw++) {
                int win = wb + kw;
                float x = 0.0f;
                if (hok && win >= 0 && win < W) x = row[win];

                float c0, w4[4];
                int   rw[4];
                eval5(x, c0, w4, rw);

                long long cf[5];
                cf[0] = pk2(c0);
#pragma unroll
                for (int t = 0; t < 4; t++) cf[t + 1] = pk2(w4[t]);

#pragma unroll
                for (int t = 0; t < 5; t++) {
                    const ulonglong2* rp = (const ulonglong2*)
                        (swr + (t == 0 ? 0 : rw[t - 1] * RSTR));
                    long long c2 = cf[t];
#pragma unroll
                    for (int q = 0; q < OT / 4; q++) {
                        ulonglong2 a = rp[q];
                        acc[2 * q]     = ffma2(c2, (long long)a.x, acc[2 * q]);
                        acc[2 * q + 1] = ffma2(c2, (long long)a.y, acc[2 * q + 1]);
                    }
                }
                swr += 9 * RSTR;
            }
        }
    }

    if (valid) {
        long long HW = (long long)Ho * Wo;
        float* ob = out + ((long long)(b * OUT + ot * OT) * Ho + ho) * Wo + wo;
#pragma unroll
        for (int k = 0; k < OT / 2; k++) {
            float2 v = upk2(acc[k]);
            ob[(2 * k) * HW]     = fmaxf(v.x, 0.0f);
            ob[(2 * k + 1) * HW] = fmaxf(v.y, 0.0f);
        }
    }
}

// ---------------------------------------------------------------------------
// 2x2 max pool
// ---------------------------------------------------------------------------
__global__ void maxpool2(const float* __restrict__ in, float* __restrict__ out,
                         int B, int C, int H, int W) {
    int Ho = H / 2, Wo = W / 2;
    int n = B * C * Ho * Wo;
    int idx = blockIdx.x * blockDim.x + threadIdx.x;
    if (idx >= n) return;
    int wo = idx % Wo;
    int t  = idx / Wo;
    int ho = t % Ho;
    t /= Ho;
    int c = t % C;
    int b = t / C;
    const float* p = in + ((long long)(b * C + c) * H + ho * 2) * W + wo * 2;
    out[idx] = fmaxf(fmaxf(p[0], p[1]), fmaxf(p[W], p[W + 1]));
}

// ---------------------------------------------------------------------------
// Head: mean(7x7) -> KAN linear 64 -> 200.  8 blocks x 25 outputs.
// ---------------------------------------------------------------------------
__global__ void classifier_kernel(const float* __restrict__ act,   // (8,64,7,7)
                                  const float* __restrict__ wp,    // [64][9][200]
                                  float* __restrict__ out) {       // (8,200)
    __shared__ float mean[512];
    __shared__ float cs[512 * 5];
    __shared__ int   cr[512 * 4];
    int tid = threadIdx.x;
    int ot  = blockIdx.x;

    for (int e = tid; e < 512; e += 256) {
        const float* p = act + e * 49;
        float s = 0.0f;
#pragma unroll
        for (int i = 0; i < 49; i++) s += p[i];
        mean[e] = s * (1.0f / 49.0f);
    }
    __syncthreads();
    for (int e = tid; e < 512; e += 256) {
        float c0, w4[4];
        int   rw[4];
        eval5(mean[e], c0, w4, rw);
        cs[e * 5 + 0] = c0;
#pragma unroll
        for (int t = 0; t < 4; t++) {
            cs[e * 5 + 1 + t] = w4[t];
            cr[e * 4 + t]     = rw[t];
        }
    }
    __syncthreads();
    if (tid < 200) {
        int b = tid / 25;
        int o = ot * 25 + tid % 25;
        float acc = 0.0f;
#pragma unroll 4
        for (int i = 0; i < 64; i++) {
            int e = b * 64 + i;
            const float* cp = &cs[e * 5];
            const int*   rp = &cr[e * 4];
            const float* wr = wp + i * 9 * 200 + o;
            acc = fmaf(cp[0], wr[0], acc);
            acc = fmaf(cp[1], wr[rp[0] * 200], acc);
            acc = fmaf(cp[2], wr[rp[1] * 200], acc);
            acc = fmaf(cp[3], wr[rp[2] * 200], acc);
            acc = fmaf(cp[4], wr[rp[3] * 200], acc);
        }
        out[b * 200 + o] = acc;
    }
}

// ---------------------------------------------------------------------------
// Host launcher
// ---------------------------------------------------------------------------
static void* sym_addr(const void* symbol) {
    void* p = nullptr;
    cudaGetSymbolAddress(&p, symbol);
    return p;
}

extern "C" void kernel_launch(void* const* d_in, const int* in_sizes, int n_in,
                              void* d_out, int out_size) {
    const float* x   = (const float*)d_in[0];
    const float* bw0 = (const float*)d_in[1];
    const float* sw0 = (const float*)d_in[2];
    const float* sc0 = (const float*)d_in[3];
    const float* bw1 = (const float*)d_in[4];
    const float* sw1 = (const float*)d_in[5];
    const float* sc1 = (const float*)d_in[6];
    const float* bw2 = (const float*)d_in[7];
    const float* sw2 = (const float*)d_in[8];
    const float* sc2 = (const float*)d_in[9];
    const float* bwc = (const float*)d_in[10];
    const float* swc = (const float*)d_in[11];
    const float* scc = (const float*)d_in[12];
    float* out = (float*)d_out;

    float* wp0 = (float*)sym_addr(g_wp0);
    float* wp1 = (float*)sym_addr(g_wp1);
    float* wp2 = (float*)sym_addr(g_wp2);
    float* wpc = (float*)sym_addr(g_wpc);
    float* a0  = (float*)sym_addr(g_a0);
    float* p0  = (float*)sym_addr(g_p0);
    float* a1  = (float*)sym_addr(g_a1);
    float* p1  = (float*)sym_addr(g_p1);
    float* a2  = (float*)sym_addr(g_a2);

    {
        int total = N0P + N1P + N2P + NCP;
        pack_all<<<(total + 255) / 256, 256>>>(bw0, sw0, sc0, bw1, sw1, sc1,
                                               bw2, sw2, sc2, bwc, swc, scc,
                                               wp0, wp1, wp2, wpc);
    }

    // layer 0: OUT=16, OT=16, 1 tile, T=128, RSTR=20, smem = 147*9*20*4 = 105840
    {
        auto k = kan_conv<3, 7, 2, 3, 16, 16, 128, 20>;
        int smem = 147 * 9 * 20 * 4;
        cudaFuncSetAttribute((const void*)k, cudaFuncAttributeMaxDynamicSharedMemorySize, smem);
        dim3 grid(8 * 112 * 112 / 128, 1);
        k<<<grid, 128, smem>>>(x, wp0, a0, 8, 224, 224, 112, 112);
        maxpool2<<<(8 * 16 * 56 * 56 + 255) / 256, 256>>>(a0, p0, 8, 16, 112, 112);
    }
    // layer 1: OUT=32, OT=16, 2 tiles, T=64, RSTR=20, smem = 144*9*20*4 = 103680
    {
        auto k = kan_conv<16, 3, 2, 1, 32, 16, 64, 20>;
        int smem = 144 * 9 * 20 * 4;
        cudaFuncSetAttribute((const void*)k, cudaFuncAttributeMaxDynamicSharedMemorySize, smem);
        dim3 grid(8 * 28 * 28 / 64, 2);
        k<<<grid, 64, smem>>>(p0, wp1, a1, 8, 56, 56, 28, 28);
        maxpool2<<<(8 * 32 * 14 * 14 + 255) / 256, 256>>>(a1, p1, 8, 32, 28, 28);
    }
    // layer 2: OUT=64, OT=8, 8 tiles, T=64, RSTR=8, smem = 288*9*8*4 = 82944
    {
        auto k = kan_conv<32, 3, 2, 1, 64, 8, 64, 8>;
        int smem = 288 * 9 * 8 * 4;
        cudaFuncSetAttribute((const void*)k, cudaFuncAttributeMaxDynamicSharedMemorySize, smem);
        dim3 grid((8 * 7 * 7 + 63) / 64, 8);
        k<<<grid, 64, smem>>>(p1, wp2, a2, 8, 14, 14, 7, 7);
    }
    classifier_kernel<<<8, 256>>>(a2, wpc, out);

    (void)in_sizes; (void)n_in; (void)out_size;
}

// round 5
// speedup vs baseline: 1.7326x; 1.7326x over previous
#include <cuda_runtime.h>
#include <math.h>

// ---------------------------------------------------------------------------
// KANConvNet round 4: occupancy fix.
//  - L0: T=672, one block/SM, grid = 1 full wave.
//  - L1/L2: channel-slice parallelism with deterministic partial-sum buffers.
// Weight layout [i][9][OUT]: row 0 = base_w, rows 1..8 = sw*sc.
// ---------------------------------------------------------------------------

__device__ float g_wp0[147 * 9 * 16];
__device__ float g_wp1[144 * 9 * 32];
__device__ float g_wp2[288 * 9 * 64];
__device__ float g_wpc[64  * 9 * 200];

__device__ float g_a0[8 * 16 * 112 * 112];
__device__ float g_p0[8 * 16 * 56 * 56];
__device__ float g_part1[4 * 8 * 32 * 28 * 28];
__device__ float g_p1[8 * 32 * 14 * 14];
__device__ float g_part2[8 * 8 * 64 * 7 * 7];
__device__ float g_a2[8 * 64 * 7 * 7];

#define N0P (147 * 9 * 16)
#define N1P (144 * 9 * 32)
#define N2P (288 * 9 * 64)
#define NCP (64  * 9 * 200)

// ---------------- packed f32x2 helpers ----------------
__device__ __forceinline__ long long pk2(float a) {
    long long r;
    asm("mov.b64 %0, {%1, %1};" : "=l"(r) : "f"(a));
    return r;
}
__device__ __forceinline__ long long ffma2(long long a, long long b, long long c) {
    long long d;
    asm("fma.rn.f32x2 %0, %1, %2, %3;" : "=l"(d) : "l"(a), "l"(b), "l"(c));
    return d;
}
__device__ __forceinline__ float2 upk2(long long a) {
    float x, y;
    asm("mov.b64 {%0, %1}, %2;" : "=f"(x), "=f"(y) : "l"(a));
    return make_float2(x, y);
}

// ---------------- coefficient evaluation ----------------
__device__ __forceinline__ void eval5(float x, float& c0, float* w, int* r) {
    float sig = 1.0f / (1.0f + __expf(-x));
    c0 = x * sig;
    float t  = fmaf(x, 2.5f, 5.5f);         // (x + 2.2) / 0.4
    float mf = floorf(t);
    bool inr = (mf >= 0.0f) && (mf <= 10.0f);
    mf = fminf(fmaxf(mf, 0.0f), 10.0f);
    float u  = t - mf;
    float u2 = u * u;
    float u3 = u2 * u;
    float om = 1.0f - u;
    const float s6 = 1.0f / 6.0f;
    float a0 = s6 * om * om * om;
    float a1 = s6 * fmaf(3.0f, u3, fmaf(-6.0f, u2, 4.0f));
    float a2 = s6 * fmaf(-3.0f, u3, fmaf(3.0f, u2, fmaf(3.0f, u, 1.0f)));
    float a3 = s6 * u3;
    int m = (int)mf;
    w[0] = (inr && m >= 3)            ? a0 : 0.0f;
    w[1] = (inr && m >= 2 && m <= 9)  ? a1 : 0.0f;
    w[2] = (inr && m >= 1 && m <= 8)  ? a2 : 0.0f;
    w[3] = (inr && m <= 7)            ? a3 : 0.0f;
#pragma unroll
    for (int t4 = 0; t4 < 4; t4++) {
        int j = m - 3 + t4;
        j = j < 0 ? 0 : (j > 7 ? 7 : j);
        r[t4] = 1 + j;
    }
}

// ---------------- merged weight packing ----------------
__device__ __forceinline__ void pack_one(int idx,
                                         const float* __restrict__ bw,
                                         const float* __restrict__ sw,
                                         const float* __restrict__ sc,
                                         float* __restrict__ wp,
                                         int OUT, int IN) {
    int i   = idx / (9 * OUT);
    int rem = idx - i * 9 * OUT;
    int r   = rem / OUT;
    int o   = rem - r * OUT;
    int oi  = o * IN + i;
    float v = (r == 0) ? bw[oi] : sw[oi * 8 + (r - 1)] * sc[oi];
    wp[idx] = v;
}

__global__ void pack_all(const float* bw0, const float* sw0, const float* sc0,
                         const float* bw1, const float* sw1, const float* sc1,
                         const float* bw2, const float* sw2, const float* sc2,
                         const float* bwc, const float* swc, const float* scc,
                         float* wp0, float* wp1, float* wp2, float* wpc) {
    int idx = blockIdx.x * blockDim.x + threadIdx.x;
    if (idx < N0P) { pack_one(idx, bw0, sw0, sc0, wp0, 16, 147); return; }
    idx -= N0P;
    if (idx < N1P) { pack_one(idx, bw1, sw1, sc1, wp1, 32, 144); return; }
    idx -= N1P;
    if (idx < N2P) { pack_one(idx, bw2, sw2, sc2, wp2, 64, 288); return; }
    idx -= N2P;
    if (idx < NCP) { pack_one(idx, bwc, swc, scc, wpc, 200, 64); }
}

// ---------------------------------------------------------------------------
// Fused KAN conv layer with channel slices.
//   blockIdx.y = sl * (OUT/OT) + ot
//   RELU=true  : write relu(y) to full NCHW output (single slice only)
//   RELU=false : write raw partial to out + sl*B*OUT*Ho*Wo
// ---------------------------------------------------------------------------
template <int CIN, int CSL, int K, int S, int P, int OUT, int OT, int T,
          int RSTR, bool RELU>
__global__ void __launch_bounds__(T)
kan_conv(const float* __restrict__ in,
         const float* __restrict__ wp,
         float* __restrict__ out,
         int B, int H, int W, int Ho, int Wo) {
    extern __shared__ float swm[];   // [CSL*K*K][9][RSTR]
    const int INF_SL = CSL * K * K;
    const int NOT    = OUT / OT;
    const int sl     = blockIdx.y / NOT;
    const int ot     = blockIdx.y - sl * NOT;

    for (int idx = threadIdx.x; idx < INF_SL * 9 * OT; idx += T) {
        int i   = idx / (9 * OT);
        int rem = idx - i * 9 * OT;
        int r   = rem / OT;
        int o   = rem - r * OT;
        swm[(i * 9 + r) * RSTR + o] =
            wp[((sl * INF_SL + i) * 9 + r) * OUT + ot * OT + o];
    }
    __syncthreads();

    const int N = B * Ho * Wo;
    int gp      = blockIdx.x * T + threadIdx.x;
    bool valid  = gp < N;
    int gpc     = valid ? gp : 0;
    int b  = gpc / (Ho * Wo);
    int rr = gpc - b * Ho * Wo;
    int ho = rr / Wo;
    int wo = rr - ho * Wo;
    int hb = ho * S - P;
    int wb = wo * S - P;
    const float* inb = in + (long long)b * CIN * H * W;

    long long acc[OT / 2];
#pragma unroll
    for (int k = 0; k < OT / 2; k++) acc[k] = 0LL;

    const float* swr = swm;
#pragma unroll 1
    for (int cl = 0; cl < CSL; cl++) {
        int c = sl * CSL + cl;
#pragma unroll 1
        for (int kh = 0; kh < K; kh++) {
            int hin = hb + kh;
            const float* row = inb + ((long long)c * H + hin) * W;
            bool hok = valid && (hin >= 0) && (hin < H);
#pragma unroll
            for (int kw = 0; kw < K; kw++) {
                int win = wb + kw;
                float x = 0.0f;
                if (hok && win >= 0 && win < W) x = row[win];

                float c0, w4[4];
                int   rw[4];
                eval5(x, c0, w4, rw);

                long long cf[5];
                cf[0] = pk2(c0);
#pragma unroll
                for (int t = 0; t < 4; t++) cf[t + 1] = pk2(w4[t]);

#pragma unroll
                for (int t = 0; t < 5; t++) {
                    const ulonglong2* rp = (const ulonglong2*)
                        (swr + (t == 0 ? 0 : rw[t - 1] * RSTR));
                    long long c2 = cf[t];
#pragma unroll
                    for (int q = 0; q < OT / 4; q++) {
                        ulonglong2 a = rp[q];
                        acc[2 * q]     = ffma2(c2, (long long)a.x, acc[2 * q]);
                        acc[2 * q + 1] = ffma2(c2, (long long)a.y, acc[2 * q + 1]);
                    }
                }
                swr += 9 * RSTR;
            }
        }
    }

    if (valid) {
        long long HW = (long long)Ho * Wo;
        float* ob = out + (RELU ? 0LL : (long long)sl * B * OUT * Ho * Wo)
                        + ((long long)(b * OUT + ot * OT) * Ho + ho) * Wo + wo;
#pragma unroll
        for (int k = 0; k < OT / 2; k++) {
            float2 v = upk2(acc[k]);
            if (RELU) {
                ob[(2 * k) * HW]     = fmaxf(v.x, 0.0f);
                ob[(2 * k + 1) * HW] = fmaxf(v.y, 0.0f);
            } else {
                ob[(2 * k) * HW]     = v.x;
                ob[(2 * k + 1) * HW] = v.y;
            }
        }
    }
}

// ---------------------------------------------------------------------------
// 2x2 max pool (input already relu'd)
// ---------------------------------------------------------------------------
__global__ void maxpool2(const float* __restrict__ in, float* __restrict__ out,
                         int B, int C, int H, int W) {
    int Ho = H / 2, Wo = W / 2;
    int n = B * C * Ho * Wo;
    int idx = blockIdx.x * blockDim.x + threadIdx.x;
    if (idx >= n) return;
    int wo = idx % Wo;
    int t  = idx / Wo;
    int ho = t % Ho;
    t /= Ho;
    int c = t % C;
    int b = t / C;
    const float* p = in + ((long long)(b * C + c) * H + ho * 2) * W + wo * 2;
    out[idx] = fmaxf(fmaxf(p[0], p[1]), fmaxf(p[W], p[W + 1]));
}

// ---------------------------------------------------------------------------
// sum NP partials -> relu -> 2x2 max pool
// ---------------------------------------------------------------------------
template <int NP>
__global__ void maxpool_sum(const float* __restrict__ in, float* __restrict__ out,
                            int B, int C, int H, int W) {
    int Ho = H / 2, Wo = W / 2;
    int n = B * C * Ho * Wo;
    long long sz = (long long)B * C * H * W;
    int idx = blockIdx.x * blockDim.x + threadIdx.x;
    if (idx >= n) return;
    int wo = idx % Wo;
    int t  = idx / Wo;
    int ho = t % Ho;
    t /= Ho;
    int c = t % C;
    int b = t / C;
    long long base = ((long long)(b * C + c) * H + ho * 2) * W + wo * 2;
    float v[4] = {0.f, 0.f, 0.f, 0.f};
#pragma unroll
    for (int p = 0; p < NP; p++) {
        const float* ip = in + p * sz + base;
        v[0] += ip[0];
        v[1] += ip[1];
        v[2] += ip[W];
        v[3] += ip[W + 1];
    }
    float m = fmaxf(fmaxf(v[0], v[1]), fmaxf(v[2], v[3]));
    out[idx] = fmaxf(m, 0.0f);
}

// ---------------------------------------------------------------------------
// sum NP partials -> relu (elementwise)
// ---------------------------------------------------------------------------
template <int NP>
__global__ void reduce_relu(const float* __restrict__ in, float* __restrict__ out,
                            int n) {
    int idx = blockIdx.x * blockDim.x + threadIdx.x;
    if (idx >= n) return;
    float s = 0.0f;
#pragma unroll
    for (int p = 0; p < NP; p++) s += in[p * n + idx];
    out[idx] = fmaxf(s, 0.0f);
}

// ---------------------------------------------------------------------------
// Head: mean(7x7) -> KAN linear 64 -> 200.  8 blocks x 25 outputs.
// ---------------------------------------------------------------------------
__global__ void classifier_kernel(const float* __restrict__ act,   // (8,64,7,7)
                                  const float* __restrict__ wp,    // [64][9][200]
                                  float* __restrict__ out) {       // (8,200)
    __shared__ float mean[512];
    __shared__ float cs[512 * 5];
    __shared__ int   cr[512 * 4];
    int tid = threadIdx.x;
    int ot  = blockIdx.x;

    for (int e = tid; e < 512; e += 256) {
        const float* p = act + e * 49;
        float s = 0.0f;
#pragma unroll
        for (int i = 0; i < 49; i++) s += p[i];
        mean[e] = s * (1.0f / 49.0f);
    }
    __syncthreads();
    for (int e = tid; e < 512; e += 256) {
        float c0, w4[4];
        int   rw[4];
        eval5(mean[e], c0, w4, rw);
        cs[e * 5 + 0] = c0;
#pragma unroll
        for (int t = 0; t < 4; t++) {
            cs[e * 5 + 1 + t] = w4[t];
            cr[e * 4 + t]     = rw[t];
        }
    }
    __syncthreads();
    if (tid < 200) {
        int b = tid / 25;
        int o = ot * 25 + tid % 25;
        float acc = 0.0f;
#pragma unroll 4
        for (int i = 0; i < 64; i++) {
            int e = b * 64 + i;
            const float* cp = &cs[e * 5];
            const int*   rp = &cr[e * 4];
            const float* wr = wp + i * 9 * 200 + o;
            acc = fmaf(cp[0], wr[0], acc);
            acc = fmaf(cp[1], wr[rp[0] * 200], acc);
            acc = fmaf(cp[2], wr[rp[1] * 200], acc);
            acc = fmaf(cp[3], wr[rp[2] * 200], acc);
            acc = fmaf(cp[4], wr[rp[3] * 200], acc);
        }
        out[b * 200 + o] = acc;
    }
}

// ---------------------------------------------------------------------------
// Host launcher
// ---------------------------------------------------------------------------
static void* sym_addr(const void* symbol) {
    void* p = nullptr;
    cudaGetSymbolAddress(&p, symbol);
    return p;
}

extern "C" void kernel_launch(void* const* d_in, const int* in_sizes, int n_in,
                              void* d_out, int out_size) {
    const float* x   = (const float*)d_in[0];
    const float* bw0 = (const float*)d_in[1];
    const float* sw0 = (const float*)d_in[2];
    const float* sc0 = (const float*)d_in[3];
    const float* bw1 = (const float*)d_in[4];
    const float* sw1 = (const float*)d_in[5];
    const float* sc1 = (const float*)d_in[6];
    const float* bw2 = (const float*)d_in[7];
    const float* sw2 = (const float*)d_in[8];
    const float* sc2 = (const float*)d_in[9];
    const float* bwc = (const float*)d_in[10];
    const float* swc = (const float*)d_in[11];
    const float* scc = (const float*)d_in[12];
    float* out = (float*)d_out;

    float* wp0   = (float*)sym_addr(g_wp0);
    float* wp1   = (float*)sym_addr(g_wp1);
    float* wp2   = (float*)sym_addr(g_wp2);
    float* wpc   = (float*)sym_addr(g_wpc);
    float* a0    = (float*)sym_addr(g_a0);
    float* p0    = (float*)sym_addr(g_p0);
    float* part1 = (float*)sym_addr(g_part1);
    float* p1    = (float*)sym_addr(g_p1);
    float* part2 = (float*)sym_addr(g_part2);
    float* a2    = (float*)sym_addr(g_a2);

    {
        int total = N0P + N1P + N2P + NCP;
        pack_all<<<(total + 255) / 256, 256>>>(bw0, sw0, sc0, bw1, sw1, sc1,
                                               bw2, sw2, sc2, bwc, swc, scc,
                                               wp0, wp1, wp2, wpc);
    }

    // L0: CIN=3 (1 slice), OUT=16, OT=16, T=672, RSTR=20, smem=105840.
    // grid = 150 blocks = 1 wave, 21 warps/SM.
    {
        auto k = kan_conv<3, 3, 7, 2, 3, 16, 16, 672, 20, true>;
        int smem = 147 * 9 * 20 * 4;
        cudaFuncSetAttribute((const void*)k, cudaFuncAttributeMaxDynamicSharedMemorySize, smem);
        dim3 grid((8 * 112 * 112 + 671) / 672, 1);
        k<<<grid, 672, smem>>>(x, wp0, a0, 8, 224, 224, 112, 112);
        maxpool2<<<(8 * 16 * 56 * 56 + 255) / 256, 256>>>(a0, p0, 8, 16, 112, 112);
    }
    // L1: 4 slices x 4ch, OUT=32, OT=32, T=256, RSTR=36, smem=36*9*36*4=46656.
    // grid = 25 x 4 = 100 blocks, 2 blocks/SM -> 16 warps/SM. Partials.
    {
        auto k = kan_conv<16, 4, 3, 2, 1, 32, 32, 256, 36, false>;
        int smem = 36 * 9 * 36 * 4;
        cudaFuncSetAttribute((const void*)k, cudaFuncAttributeMaxDynamicSharedMemorySize, smem);
        dim3 grid((8 * 28 * 28 + 255) / 256, 4);
        k<<<grid, 256, smem>>>(p0, wp1, part1, 8, 56, 56, 28, 28);
        maxpool_sum<4><<<(8 * 32 * 14 * 14 + 255) / 256, 256>>>(part1, p1, 8, 32, 28, 28);
    }
    // L2: 8 slices x 4ch, OUT=64, OT=32 (2 tiles), T=64, RSTR=36, smem=46656.
    // grid = 7 x 16 = 112 blocks. Partials -> reduce_relu.
    {
        auto k = kan_conv<32, 4, 3, 2, 1, 64, 32, 64, 36, false>;
        int smem = 36 * 9 * 36 * 4;
        cudaFuncSetAttribute((const void*)k, cudaFuncAttributeMaxDynamicSharedMemorySize, smem);
        dim3 grid((8 * 7 * 7 + 63) / 64, 16);
        k<<<grid, 64, smem>>>(p1, wp2, part2, 8, 14, 14, 7, 7);
        reduce_relu<8><<<(8 * 64 * 7 * 7 + 255) / 256, 256>>>(part2, a2, 8 * 64 * 7 * 7);
    }
    classifier_kernel<<<8, 256>>>(a2, wpc, out);

    (void)in_sizes; (void)n_in; (void)out_size;
}

// round 6
// speedup vs baseline: 1.8410x; 1.0626x over previous
#include <cuda_runtime.h>
#include <math.h>

// ---------------------------------------------------------------------------
// KANConvNet round 5: per-pixel phi precompute (SoA 9 planes) + dense
// gather-GEMM with block-uniform broadcast weight rows (no smem divergence).
//
//   L0: cin=3,  cout=16, k=7, s=2, p=3 : 224->112 -> pool 56   (3 K-slices)
//   L1: cin=16, cout=32, k=3, s=2, p=1 : 56->28   -> pool 14   (12 K-slices)
//   L2: cin=32, cout=64, k=3, s=2, p=1 : 14->7                 (36 K-slices)
//   head: mean(7x7) -> kan_linear(64 -> 200)
//
// Weights [f][9][OUT]: row 0 = base_w, rows 1..8 = sw*sc (spline j = r-1).
// phi[r][pixel]: r=0 silu(x); r=1..8 dense cardinal-cubic coefficients.
// Padded (out-of-bounds) taps use PHI(0) = {0,0,0,1/48,23/48,23/48,1/48,0,0}.
// ---------------------------------------------------------------------------

#define NPIX0 (8 * 3 * 224 * 224)
#define NPIX1 (8 * 16 * 56 * 56)
#define NPIX2 (8 * 32 * 14 * 14)

__device__ float g_wp0[147 * 9 * 16];
__device__ float g_wp1[144 * 9 * 32];
__device__ float g_wp2[288 * 9 * 64];
__device__ float g_wpc[64  * 9 * 200];

__device__ float g_phi0[9 * NPIX0];
__device__ float g_part0[3 * 8 * 16 * 112 * 112];
__device__ float g_p0[NPIX1];
__device__ float g_phi1[9 * NPIX1];
__device__ float g_part1[12 * 8 * 32 * 28 * 28];
__device__ float g_p1[NPIX2];
__device__ float g_phi2[9 * NPIX2];
__device__ float g_part2[36 * 8 * 64 * 7 * 7];
__device__ float g_a2[8 * 64 * 7 * 7];

#define N0P (147 * 9 * 16)
#define N1P (144 * 9 * 32)
#define N2P (288 * 9 * 64)
#define NCP (64  * 9 * 200)

// ---------------- packed f32x2 helpers ----------------
__device__ __forceinline__ long long pk2(float a) {
    long long r;
    asm("mov.b64 %0, {%1, %1};" : "=l"(r) : "f"(a));
    return r;
}
__device__ __forceinline__ long long ffma2(long long a, long long b, long long c) {
    long long d;
    asm("fma.rn.f32x2 %0, %1, %2, %3;" : "=l"(d) : "l"(a), "l"(b), "l"(c));
    return d;
}
__device__ __forceinline__ float2 upk2(long long a) {
    float x, y;
    asm("mov.b64 {%0, %1}, %2;" : "=f"(x), "=f"(y) : "l"(a));
    return make_float2(x, y);
}

// ---------------- dense 9-coefficient evaluation ----------------
__device__ __forceinline__ void eval9(float x, float* c) {
    float sig = 1.0f / (1.0f + __expf(-x));
    c[0] = x * sig;
    float t  = fmaf(x, 2.5f, 5.5f);          // (x + 2.2) / 0.4
    float mf = floorf(t);
    bool inr = (mf >= 0.0f) && (mf <= 10.0f);
    mf = fminf(fmaxf(mf, 0.0f), 10.0f);
    float u  = t - mf;
    float u2 = u * u;
    float u3 = u2 * u;
    float om = 1.0f - u;
    const float s6 = 1.0f / 6.0f;
    float w0 = s6 * om * om * om;
    float w1 = s6 * fmaf(3.0f, u3, fmaf(-6.0f, u2, 4.0f));
    float w2 = s6 * fmaf(-3.0f, u3, fmaf(3.0f, u2, fmaf(3.0f, u, 1.0f)));
    float w3 = s6 * u3;
    int m = (int)mf;
#pragma unroll
    for (int r = 1; r < 9; r++) {
        int tt = (r - 1) - (m - 3);
        float cv = 0.0f;
        cv = (tt == 0) ? w0 : cv;
        cv = (tt == 1) ? w1 : cv;
        cv = (tt == 2) ? w2 : cv;
        cv = (tt == 3) ? w3 : cv;
        c[r] = inr ? cv : 0.0f;
    }
}

// eval5 variant for the classifier head (sparse gather version)
__device__ __forceinline__ void eval5(float x, float& c0, float* w, int* r) {
    float sig = 1.0f / (1.0f + __expf(-x));
    c0 = x * sig;
    float t  = fmaf(x, 2.5f, 5.5f);
    float mf = floorf(t);
    bool inr = (mf >= 0.0f) && (mf <= 10.0f);
    mf = fminf(fmaxf(mf, 0.0f), 10.0f);
    float u  = t - mf;
    float u2 = u * u;
    float u3 = u2 * u;
    float om = 1.0f - u;
    const float s6 = 1.0f / 6.0f;
    float a0 = s6 * om * om * om;
    float a1 = s6 * fmaf(3.0f, u3, fmaf(-6.0f, u2, 4.0f));
    float a2 = s6 * fmaf(-3.0f, u3, fmaf(3.0f, u2, fmaf(3.0f, u, 1.0f)));
    float a3 = s6 * u3;
    int m = (int)mf;
    w[0] = (inr && m >= 3)            ? a0 : 0.0f;
    w[1] = (inr && m >= 2 && m <= 9)  ? a1 : 0.0f;
    w[2] = (inr && m >= 1 && m <= 8)  ? a2 : 0.0f;
    w[3] = (inr && m <= 7)            ? a3 : 0.0f;
#pragma unroll
    for (int t4 = 0; t4 < 4; t4++) {
        int j = m - 3 + t4;
        j = j < 0 ? 0 : (j > 7 ? 7 : j);
        r[t4] = 1 + j;
    }
}

// ---------------- phi precompute: x[pixel] -> phi[9][pixel] ----------------
__global__ void phi_eval(const float* __restrict__ x, float* __restrict__ phi,
                         int n) {
    int i = blockIdx.x * blockDim.x + threadIdx.x;
    if (i >= n) return;
    float c[9];
    eval9(x[i], c);
#pragma unroll
    for (int r = 0; r < 9; r++) phi[r * n + i] = c[r];
}

// ---------------- merged weight packing ----------------
__device__ __forceinline__ void pack_one(int idx,
                                         const float* __restrict__ bw,
                                         const float* __restrict__ sw,
                                         const float* __restrict__ sc,
                                         float* __restrict__ wp,
                                         int OUT, int IN) {
    int i   = idx / (9 * OUT);
    int rem = idx - i * 9 * OUT;
    int r   = rem / OUT;
    int o   = rem - r * OUT;
    int oi  = o * IN + i;
    float v = (r == 0) ? bw[oi] : sw[oi * 8 + (r - 1)] * sc[oi];
    wp[idx] = v;
}

__global__ void pack_all(const float* bw0, const float* sw0, const float* sc0,
                         const float* bw1, const float* sw1, const float* sc1,
                         const float* bw2, const float* sw2, const float* sc2,
                         const float* bwc, const float* swc, const float* scc,
                         float* wp0, float* wp1, float* wp2, float* wpc) {
    int idx = blockIdx.x * blockDim.x + threadIdx.x;
    if (idx < N0P) { pack_one(idx, bw0, sw0, sc0, wp0, 16, 147); return; }
    idx -= N0P;
    if (idx < N1P) { pack_one(idx, bw1, sw1, sc1, wp1, 32, 144); return; }
    idx -= N1P;
    if (idx < N2P) { pack_one(idx, bw2, sw2, sc2, wp2, 64, 288); return; }
    idx -= N2P;
    if (idx < NCP) { pack_one(idx, bwc, swc, scc, wpc, 200, 64); }
}

// ---------------------------------------------------------------------------
// Dense gather-GEMM conv. grid.y = sl * (OUT/OT) + ot. Writes raw partial
// sums for K-slice sl into out + sl*B*OUT*Ho*Wo.
// ---------------------------------------------------------------------------
template <int CIN, int K, int S, int P, int OUT, int OT, int PX, int T, int FSL>
__global__ void __launch_bounds__(T, 3)
kan_conv_g(const float* __restrict__ phi,   // [9][B*CIN*H*W]
           const float* __restrict__ wp,    // [F][9][OUT]
           float* __restrict__ out,
           int B, int H, int W, int Ho, int Wo) {
    __shared__ float swm[FSL * 9 * OT];
    const int NOT  = OUT / OT;
    const int sl   = blockIdx.y / NOT;
    const int ot   = blockIdx.y - sl * NOT;
    const int NPIX = B * CIN * H * W;

    for (int idx = threadIdx.x; idx < FSL * 9 * OT; idx += T) {
        int f   = idx / (9 * OT);
        int rem = idx - f * 9 * OT;
        int r   = rem / OT;
        int o   = rem - r * OT;
        swm[idx] = wp[((sl * FSL + f) * 9 + r) * OUT + ot * OT + o];
    }
    __syncthreads();

    const float* pl[9];
#pragma unroll
    for (int r = 0; r < 9; r++) pl[r] = phi + (long long)r * NPIX;

    const float PHI_PAD[9] = {0.0f, 0.0f, 0.0f,
                              1.0f / 48.0f, 23.0f / 48.0f,
                              23.0f / 48.0f, 1.0f / 48.0f,
                              0.0f, 0.0f};

    const int N = B * Ho * Wo;
    int  hoS[PX], woS[PX], pbase[PX];
    bool pv[PX];
#pragma unroll
    for (int p = 0; p < PX; p++) {
        int gp = blockIdx.x * T * PX + p * T + threadIdx.x;
        pv[p]  = gp < N;
        int g  = pv[p] ? gp : 0;
        int b  = g / (Ho * Wo);
        int rr = g - b * Ho * Wo;
        int ho = rr / Wo;
        int wo = rr - ho * Wo;
        hoS[p]   = ho * S - P;
        woS[p]   = wo * S - P;
        pbase[p] = b * CIN * H * W;
    }

    long long acc[PX][OT / 2];
#pragma unroll
    for (int p = 0; p < PX; p++)
#pragma unroll
        for (int k = 0; k < OT / 2; k++) acc[p][k] = 0LL;

#pragma unroll 1
    for (int fl = 0; fl < FSL; fl++) {
        int f   = sl * FSL + fl;
        int c   = f / (K * K);
        int rem = f - c * K * K;
        int kh  = rem / K;
        int kw  = rem - kh * K;

        float cr[PX][9];
#pragma unroll
        for (int p = 0; p < PX; p++) {
            int hin = hoS[p] + kh;
            int win = woS[p] + kw;
            bool v  = pv[p] && (hin >= 0) && (hin < H) && (win >= 0) && (win < W);
            int idx = v ? (pbase[p] + (c * H + hin) * W + win) : 0;
#pragma unroll
            for (int r = 0; r < 9; r++)
                cr[p][r] = v ? __ldg(pl[r] + idx) : PHI_PAD[r];
        }

        const float* wr = swm + fl * 9 * OT;
#pragma unroll
        for (int r = 0; r < 9; r++) {
            const ulonglong2* wv = (const ulonglong2*)(wr + r * OT);
#pragma unroll
            for (int p = 0; p < PX; p++) {
                long long cp = pk2(cr[p][r]);
#pragma unroll
                for (int q = 0; q < OT / 4; q++) {
                    ulonglong2 a = wv[q];
                    acc[p][2 * q]     = ffma2(cp, (long long)a.x, acc[p][2 * q]);
                    acc[p][2 * q + 1] = ffma2(cp, (long long)a.y, acc[p][2 * q + 1]);
                }
            }
        }
    }

    long long HW = (long long)Ho * Wo;
    float* ob = out + (long long)sl * B * OUT * HW;
#pragma unroll
    for (int p = 0; p < PX; p++) {
        if (!pv[p]) continue;
        int gp = blockIdx.x * T * PX + p * T + threadIdx.x;
        int b  = gp / (Ho * Wo);
        int rr = gp - b * Ho * Wo;
        float* op = ob + (long long)(b * OUT + ot * OT) * HW + rr;
#pragma unroll
        for (int k = 0; k < OT / 2; k++) {
            float2 v = upk2(acc[p][k]);
            op[(2 * k) * HW]     = v.x;
            op[(2 * k + 1) * HW] = v.y;
        }
    }
}

// ---------------------------------------------------------------------------
// sum NP partials -> 2x2 max pool -> relu
// ---------------------------------------------------------------------------
template <int NP>
__global__ void maxpool_sum(const float* __restrict__ in, float* __restrict__ out,
                            int B, int C, int H, int W) {
    int Ho = H / 2, Wo = W / 2;
    int n = B * C * Ho * Wo;
    long long sz = (long long)B * C * H * W;
    int idx = blockIdx.x * blockDim.x + threadIdx.x;
    if (idx >= n) return;
    int wo = idx % Wo;
    int t  = idx / Wo;
    int ho = t % Ho;
    t /= Ho;
    int c = t % C;
    int b = t / C;
    long long base = ((long long)(b * C + c) * H + ho * 2) * W + wo * 2;
    float v[4] = {0.f, 0.f, 0.f, 0.f};
#pragma unroll
    for (int p = 0; p < NP; p++) {
        const float* ip = in + p * sz + base;
        v[0] += ip[0];
        v[1] += ip[1];
        v[2] += ip[W];
        v[3] += ip[W + 1];
    }
    float m = fmaxf(fmaxf(v[0], v[1]), fmaxf(v[2], v[3]));
    out[idx] = fmaxf(m, 0.0f);
}

// ---------------------------------------------------------------------------
// sum NP partials -> relu (elementwise)
// ---------------------------------------------------------------------------
template <int NP>
__global__ void reduce_relu(const float* __restrict__ in, float* __restrict__ out,
                            int n) {
    int idx = blockIdx.x * blockDim.x + threadIdx.x;
    if (idx >= n) return;
    float s = 0.0f;
#pragma unroll
    for (int p = 0; p < NP; p++) s += in[(long long)p * n + idx];
    out[idx] = fmaxf(s, 0.0f);
}

// ---------------------------------------------------------------------------
// Head: mean(7x7) -> KAN linear 64 -> 200.  8 blocks x 25 outputs.
// ---------------------------------------------------------------------------
__global__ void classifier_kernel(const float* __restrict__ act,
                                  const float* __restrict__ wp,
                                  float* __restrict__ out) {
    __shared__ float mean[512];
    __shared__ float cs[512 * 5];
    __shared__ int   cr[512 * 4];
    int tid = threadIdx.x;
    int ot  = blockIdx.x;

    for (int e = tid; e < 512; e += 256) {
        const float* p = act + e * 49;
        float s = 0.0f;
#pragma unroll
        for (int i = 0; i < 49; i++) s += p[i];
        mean[e] = s * (1.0f / 49.0f);
    }
    __syncthreads();
    for (int e = tid; e < 512; e += 256) {
        float c0, w4[4];
        int   rw[4];
        eval5(mean[e], c0, w4, rw);
        cs[e * 5 + 0] = c0;
#pragma unroll
        for (int t = 0; t < 4; t++) {
            cs[e * 5 + 1 + t] = w4[t];
            cr[e * 4 + t]     = rw[t];
        }
    }
    __syncthreads();
    if (tid < 200) {
        int b = tid / 25;
        int o = ot * 25 + tid % 25;
        float acc = 0.0f;
#pragma unroll 4
        for (int i = 0; i < 64; i++) {
            int e = b * 64 + i;
            const float* cp = &cs[e * 5];
            const int*   rp = &cr[e * 4];
            const float* wr = wp + i * 9 * 200 + o;
            acc = fmaf(cp[0], wr[0], acc);
            acc = fmaf(cp[1], wr[rp[0] * 200], acc);
            acc = fmaf(cp[2], wr[rp[1] * 200], acc);
            acc = fmaf(cp[3], wr[rp[2] * 200], acc);
            acc = fmaf(cp[4], wr[rp[3] * 200], acc);
        }
        out[b * 200 + o] = acc;
    }
}

// ---------------------------------------------------------------------------
// Host launcher
// ---------------------------------------------------------------------------
static void* sym_addr(const void* symbol) {
    void* p = nullptr;
    cudaGetSymbolAddress(&p, symbol);
    return p;
}

extern "C" void kernel_launch(void* const* d_in, const int* in_sizes, int n_in,
                              void* d_out, int out_size) {
    const float* x   = (const float*)d_in[0];
    const float* bw0 = (const float*)d_in[1];
    const float* sw0 = (const float*)d_in[2];
    const float* sc0 = (const float*)d_in[3];
    const float* bw1 = (const float*)d_in[4];
    const float* sw1 = (const float*)d_in[5];
    const float* sc1 = (const float*)d_in[6];
    const float* bw2 = (const float*)d_in[7];
    const float* sw2 = (const float*)d_in[8];
    const float* sc2 = (const float*)d_in[9];
    const float* bwc = (const float*)d_in[10];
    const float* swc = (const float*)d_in[11];
    const float* scc = (const float*)d_in[12];
    float* out = (float*)d_out;

    float* wp0   = (float*)sym_addr(g_wp0);
    float* wp1   = (float*)sym_addr(g_wp1);
    float* wp2   = (float*)sym_addr(g_wp2);
    float* wpc   = (float*)sym_addr(g_wpc);
    float* phi0  = (float*)sym_addr(g_phi0);
    float* part0 = (float*)sym_addr(g_part0);
    float* p0    = (float*)sym_addr(g_p0);
    float* phi1  = (float*)sym_addr(g_phi1);
    float* part1 = (float*)sym_addr(g_part1);
    float* p1    = (float*)sym_addr(g_p1);
    float* phi2  = (float*)sym_addr(g_phi2);
    float* part2 = (float*)sym_addr(g_part2);
    float* a2    = (float*)sym_addr(g_a2);

    {
        int total = N0P + N1P + N2P + NCP;
        pack_all<<<(total + 255) / 256, 256>>>(bw0, sw0, sc0, bw1, sw1, sc1,
                                               bw2, sw2, sc2, bwc, swc, scc,
                                               wp0, wp1, wp2, wpc);
    }

    // ---- L0 ----
    phi_eval<<<(NPIX0 + 255) / 256, 256>>>(x, phi0, NPIX0);
    {
        // 196 pos-tiles (512 pos each) x 3 K-slices (49 feat)
        auto k = kan_conv_g<3, 7, 2, 3, 16, 16, 4, 128, 49>;
        dim3 grid(196, 3);
        k<<<grid, 128>>>(phi0, wp0, part0, 8, 224, 224, 112, 112);
        maxpool_sum<3><<<(NPIX1 + 255) / 256, 256>>>(part0, p0, 8, 16, 112, 112);
    }
    // ---- L1 ----
    phi_eval<<<(NPIX1 + 255) / 256, 256>>>(p0, phi1, NPIX1);
    {
        // 13 pos-tiles x (12 K-slices x 2 o-tiles)
        auto k = kan_conv_g<16, 3, 2, 1, 32, 16, 4, 128, 12>;
        dim3 grid(13, 24);
        k<<<grid, 128>>>(phi1, wp1, part1, 8, 56, 56, 28, 28);
        maxpool_sum<12><<<(NPIX2 + 255) / 256, 256>>>(part1, p1, 8, 32, 28, 28);
    }
    // ---- L2 ----
    phi_eval<<<(NPIX2 + 255) / 256, 256>>>(p1, phi2, NPIX2);
    {
        // 4 pos-tiles (PX=1) x (36 K-slices x 4 o-tiles)
        auto k = kan_conv_g<32, 3, 2, 1, 64, 16, 1, 128, 8>;
        dim3 grid(4, 144);
        k<<<grid, 128>>>(phi2, wp2, part2, 8, 14, 14, 7, 7);
        reduce_relu<36><<<(8 * 64 * 7 * 7 + 255) / 256, 256>>>(part2, a2, 8 * 64 * 7 * 7);
    }
    classifier_kernel<<<8, 256>>>(a2, wpc, out);

    (void)in_sizes; (void)n_in; (void)out_size;
}